// round 3
// baseline (speedup 1.0000x reference)
#include <cuda_runtime.h>
#include <math.h>

#define BQ 8
#define SEQ 1024
#define DIMV 512
#define HEADS 8
#define DHEAD 64
#define NHEADS 64        // BQ*HEADS
#define QKVW 1536        // 3*HEADS*DHEAD
#define CH 16            // heads per L2-resident chunk

#define MU_C (1.0f/1024.0f)
#define NU_C (1.0f/1024.0f)

// ---------------- scratch (device globals; no allocations allowed) ----------
__device__ float g_qkv[(size_t)BQ * SEQ * QKVW];
__device__ float g_E[(size_t)NHEADS * SEQ * SEQ];   // E = exp(-C)
__device__ float g_r[NHEADS * SEQ];
__device__ float g_rowsum[NHEADS * SEQ];
__device__ float g_cs1[NHEADS * SEQ];
__device__ float g_cs2[NHEADS * SEQ];
__device__ float g_cs3[NHEADS * SEQ];
__device__ float g_ho[(size_t)BQ * SEQ * DIMV];

// ---------------- generic 128x128x8 fp32 GEMM, 8x8 per thread ---------------
__global__ __launch_bounds__(256) void sgemm128(
    const float* __restrict__ A, const float* __restrict__ Bm,
    float* __restrict__ C, int M, int Nn, int K, const float* __restrict__ bias)
{
    __shared__ float As[8][128];
    __shared__ float Bs[8][128];
    const int t = threadIdx.x;
    const int m0 = blockIdx.y * 128, n0 = blockIdx.x * 128;
    const int alr = t >> 1, alc = (t & 1) * 4;
    const int blr = t >> 5, blc = (t & 31) * 4;
    const int tx = t & 15, ty = t >> 4;

    float acc[8][8];
#pragma unroll
    for (int r = 0; r < 8; r++)
#pragma unroll
        for (int c = 0; c < 8; c++) acc[r][c] = 0.f;

    for (int k0 = 0; k0 < K; k0 += 8) {
        float4 av = *(const float4*)(A + (size_t)(m0 + alr) * K + k0 + alc);
        As[alc + 0][alr] = av.x; As[alc + 1][alr] = av.y;
        As[alc + 2][alr] = av.z; As[alc + 3][alr] = av.w;
        *(float4*)(&Bs[blr][blc]) =
            *(const float4*)(Bm + (size_t)(k0 + blr) * Nn + n0 + blc);
        __syncthreads();
#pragma unroll
        for (int kk = 0; kk < 8; kk++) {
            float a[8], b[8];
#pragma unroll
            for (int r = 0; r < 4; r++) {
                a[r]     = As[kk][ty * 4 + r];
                a[4 + r] = As[kk][64 + ty * 4 + r];
            }
#pragma unroll
            for (int c = 0; c < 4; c++) {
                b[c]     = Bs[kk][tx * 4 + c];
                b[4 + c] = Bs[kk][64 + tx * 4 + c];
            }
#pragma unroll
            for (int r = 0; r < 8; r++)
#pragma unroll
                for (int c = 0; c < 8; c++) acc[r][c] = fmaf(a[r], b[c], acc[r][c]);
        }
        __syncthreads();
    }
#pragma unroll
    for (int r = 0; r < 8; r++) {
        int gr = m0 + ((r < 4) ? (ty * 4 + r) : (64 + ty * 4 + (r - 4)));
#pragma unroll
        for (int half = 0; half < 2; half++) {
            int gc = n0 + ((half == 0) ? tx * 4 : 64 + tx * 4);
            float4 o;
            o.x = acc[r][half * 4 + 0]; o.y = acc[r][half * 4 + 1];
            o.z = acc[r][half * 4 + 2]; o.w = acc[r][half * 4 + 3];
            if (bias) {
                o.x += bias[gc]; o.y += bias[gc + 1];
                o.z += bias[gc + 2]; o.w += bias[gc + 3];
            }
            *(float4*)(C + (size_t)gr * Nn + gc) = o;
        }
    }
}

// -------- per-head dots -> E = exp(-scale*dots), fused first row-sum --------
__global__ __launch_bounds__(256) void qk_dots_exp(
    const float* __restrict__ qkv, float* __restrict__ E,
    float* __restrict__ rowsum, int bh0)
{
    const int bh = bh0 + blockIdx.z, b = bh >> 3, h = bh & 7;
    const int i0 = blockIdx.y * 128, j0 = blockIdx.x * 128;
    const float* qbase = qkv + (size_t)b * SEQ * QKVW + h * DHEAD;
    const float* kbase = qkv + (size_t)b * SEQ * QKVW + 512 + h * DHEAD;

    __shared__ float Qs[8][128];
    __shared__ float Ks[8][128];
    const int t = threadIdx.x;
    const int lr = t >> 1, lc = (t & 1) * 4;
    const int tx = t & 15, ty = t >> 4;

    float acc[8][8];
#pragma unroll
    for (int r = 0; r < 8; r++)
#pragma unroll
        for (int c = 0; c < 8; c++) acc[r][c] = 0.f;

    for (int k0 = 0; k0 < DHEAD; k0 += 8) {
        float4 qv = *(const float4*)(qbase + (size_t)(i0 + lr) * QKVW + k0 + lc);
        Qs[lc + 0][lr] = qv.x; Qs[lc + 1][lr] = qv.y;
        Qs[lc + 2][lr] = qv.z; Qs[lc + 3][lr] = qv.w;
        float4 kv = *(const float4*)(kbase + (size_t)(j0 + lr) * QKVW + k0 + lc);
        Ks[lc + 0][lr] = kv.x; Ks[lc + 1][lr] = kv.y;
        Ks[lc + 2][lr] = kv.z; Ks[lc + 3][lr] = kv.w;
        __syncthreads();
#pragma unroll
        for (int kk = 0; kk < 8; kk++) {
            float a[8], b[8];
#pragma unroll
            for (int r = 0; r < 4; r++) {
                a[r]     = Qs[kk][ty * 4 + r];
                a[4 + r] = Qs[kk][64 + ty * 4 + r];
            }
#pragma unroll
            for (int c = 0; c < 4; c++) {
                b[c]     = Ks[kk][tx * 4 + c];
                b[4 + c] = Ks[kk][64 + tx * 4 + c];
            }
#pragma unroll
            for (int r = 0; r < 8; r++)
#pragma unroll
                for (int c = 0; c < 8; c++) acc[r][c] = fmaf(a[r], b[c], acc[r][c]);
        }
        __syncthreads();
    }
    float* Ep = E + (size_t)bh * SEQ * SEQ;
    float rsum[8];
#pragma unroll
    for (int r = 0; r < 8; r++) rsum[r] = 0.f;
#pragma unroll
    for (int r = 0; r < 8; r++) {
        int gi = i0 + ((r < 4) ? (ty * 4 + r) : (64 + ty * 4 + (r - 4)));
#pragma unroll
        for (int half = 0; half < 2; half++) {
            int gj = j0 + ((half == 0) ? tx * 4 : 64 + tx * 4);
            float4 o;
            o.x = __expf(-0.125f * acc[r][half * 4 + 0]);
            o.y = __expf(-0.125f * acc[r][half * 4 + 1]);
            o.z = __expf(-0.125f * acc[r][half * 4 + 2]);
            o.w = __expf(-0.125f * acc[r][half * 4 + 3]);
            rsum[r] += o.x + o.y + o.z + o.w;
            *(float4*)(Ep + (size_t)gi * SEQ + gj) = o;
        }
    }
#pragma unroll
    for (int r = 0; r < 8; r++) {
#pragma unroll
        for (int off = 1; off < 16; off <<= 1)
            rsum[r] += __shfl_xor_sync(0xffffffffu, rsum[r], off);
    }
    if (tx == 0) {
#pragma unroll
        for (int r = 0; r < 8; r++) {
            int gi = i0 + ((r < 4) ? (ty * 4 + r) : (64 + ty * 4 + (r - 4)));
            atomicAdd(&rowsum[bh * SEQ + gi], rsum[r]);
        }
    }
}

// ---- colsum_j += sum_i E_ij * r_i (64-row chunks; r from rvec or MU/rvec) --
__global__ __launch_bounds__(256) void colpass(
    const float* __restrict__ E, const float* __restrict__ rvec,
    float* __restrict__ colsum, int bh0, int recip)
{
    const int bh = bh0 + blockIdx.y;
    const int i0 = blockIdx.x * 64;
    const int t = threadIdx.x;
    __shared__ float rs[64];
    if (t < 64) {
        float rv = rvec[bh * SEQ + i0 + t];
        rs[t] = recip ? (MU_C / rv) : rv;
    }
    __syncthreads();

    const float* Ep = E + (size_t)bh * SEQ * SEQ + (size_t)i0 * SEQ;
    const int j = t * 4;
    float ax = 0.f, ay = 0.f, az = 0.f, aw = 0.f;
#pragma unroll 4
    for (int i = 0; i < 64; i++) {
        float4 e = *(const float4*)(Ep + (size_t)i * SEQ + j);
        float rv = rs[i];
        ax = fmaf(e.x, rv, ax); ay = fmaf(e.y, rv, ay);
        az = fmaf(e.z, rv, az); aw = fmaf(e.w, rv, aw);
    }
    atomicAdd(&colsum[bh * SEQ + j + 0], ax);
    atomicAdd(&colsum[bh * SEQ + j + 1], ay);
    atomicAdd(&colsum[bh * SEQ + j + 2], az);
    atomicAdd(&colsum[bh * SEQ + j + 3], aw);
}

// ---- r_i = MU / sum_j E_ij * (NU/colsum_j)   (one warp per row) ------------
__global__ __launch_bounds__(256) void rowpass(
    const float* __restrict__ E, const float* __restrict__ colsum,
    float* __restrict__ r, int bh0)
{
    const int bh = bh0 + blockIdx.y;
    const int t = threadIdx.x, lane = t & 31, w = t >> 5;
    const int row = blockIdx.x * 8 + w;
    __shared__ float cs[SEQ];
    {
        float4 cv = *(const float4*)(colsum + bh * SEQ + t * 4);
        cs[t * 4 + 0] = NU_C / cv.x;
        cs[t * 4 + 1] = NU_C / cv.y;
        cs[t * 4 + 2] = NU_C / cv.z;
        cs[t * 4 + 3] = NU_C / cv.w;
    }
    __syncthreads();

    const float* Er = E + (size_t)bh * SEQ * SEQ + (size_t)row * SEQ;
    float acc = 0.f;
#pragma unroll
    for (int it = 0; it < 8; it++) {
        int j = it * 128 + lane * 4;
        float4 e = *(const float4*)(Er + j);
        acc += e.x * cs[j] + e.y * cs[j + 1] + e.z * cs[j + 2] + e.w * cs[j + 3];
    }
#pragma unroll
    for (int o = 16; o > 0; o >>= 1)
        acc += __shfl_xor_sync(0xffffffffu, acc, o);
    if (lane == 0) r[bh * SEQ + row] = MU_C / acc;
}

__global__ void init_sums(float* __restrict__ rowsum, float* __restrict__ c1,
                          float* __restrict__ c2, float* __restrict__ c3)
{
    int i = blockIdx.x * 256 + threadIdx.x;
    rowsum[i] = 0.f; c1[i] = 0.f; c2[i] = 0.f; c3[i] = 0.f;
}

// -------- per-head GEMM: ho = rn_i * (E @ (c_j V)), fused attn write --------
// block: 128 threads, tile 128 rows x 64 (=DHEAD) cols, acc 8x8 per thread
__global__ __launch_bounds__(128) void av_gemm(
    const float* __restrict__ E, const float* __restrict__ r,
    const float* __restrict__ colsum3, const float* __restrict__ qkv,
    float* __restrict__ attn, float* __restrict__ ho, int write_attn)
{
    const int bh = blockIdx.y, b = bh >> 3, h = bh & 7;
    const int i0 = blockIdx.x * 128;
    const int t = threadIdx.x;
    const int tx = t & 7, ty = t >> 3;     // 8 cols x 16 rows of threads

    __shared__ float Es[128][33];          // [i][k] padded
    __shared__ float Ws[32][64];           // c-scaled V tile [k][d]
    __shared__ float cr[SEQ];              // c_j = NU/colsum3
    __shared__ float rn[128];              // r_i * 1024

    if (t < 128) rn[t] = r[bh * SEQ + i0 + t] * 1024.0f;
#pragma unroll
    for (int q = 0; q < 8; q++) {
        int j = t + 128 * q;
        cr[j] = NU_C / colsum3[bh * SEQ + j];
    }
    __syncthreads();

    const float* Ep = E + (size_t)bh * SEQ * SEQ;
    const float* vb = qkv + (size_t)b * SEQ * QKVW + 1024 + h * DHEAD;
    float* ap = attn + (size_t)bh * SEQ * SEQ;

    float acc[8][8];
#pragma unroll
    for (int rr = 0; rr < 8; rr++)
#pragma unroll
        for (int cc = 0; cc < 8; cc++) acc[rr][cc] = 0.f;

    for (int jt = 0; jt < 32; jt++) {
        const int j0 = jt * 32;
        // load E tile 128x32 (+ fused attn write)
#pragma unroll
        for (int q = 0; q < 8; q++) {
            int f = t + 128 * q;
            int i = f >> 3, jq = (f & 7) * 4;
            float4 e = *(const float4*)(Ep + (size_t)(i0 + i) * SEQ + j0 + jq);
            Es[i][jq + 0] = e.x; Es[i][jq + 1] = e.y;
            Es[i][jq + 2] = e.z; Es[i][jq + 3] = e.w;
            if (write_attn) {
                float rv = rn[i];
                float4 o;
                o.x = rv * e.x * cr[j0 + jq + 0];
                o.y = rv * e.y * cr[j0 + jq + 1];
                o.z = rv * e.z * cr[j0 + jq + 2];
                o.w = rv * e.w * cr[j0 + jq + 3];
                *(float4*)(ap + (size_t)(i0 + i) * SEQ + j0 + jq) = o;
            }
        }
        // load V tile 32x64, scale by c_j
#pragma unroll
        for (int q = 0; q < 4; q++) {
            int f = t + 128 * q;
            int k = f >> 4, dq = (f & 15) * 4;
            float4 v = *(const float4*)(vb + (size_t)(j0 + k) * QKVW + dq);
            float cw = cr[j0 + k];
            v.x *= cw; v.y *= cw; v.z *= cw; v.w *= cw;
            *(float4*)(&Ws[k][dq]) = v;
        }
        __syncthreads();
#pragma unroll
        for (int kk = 0; kk < 32; kk++) {
            float a[8], bb[8];
#pragma unroll
            for (int rr = 0; rr < 8; rr++) a[rr] = Es[ty * 8 + rr][kk];
            float4 B0 = *(const float4*)(&Ws[kk][tx * 8]);
            float4 B1 = *(const float4*)(&Ws[kk][tx * 8 + 4]);
            bb[0] = B0.x; bb[1] = B0.y; bb[2] = B0.z; bb[3] = B0.w;
            bb[4] = B1.x; bb[5] = B1.y; bb[6] = B1.z; bb[7] = B1.w;
#pragma unroll
            for (int rr = 0; rr < 8; rr++)
#pragma unroll
                for (int cc = 0; cc < 8; cc++)
                    acc[rr][cc] = fmaf(a[rr], bb[cc], acc[rr][cc]);
        }
        __syncthreads();
    }
#pragma unroll
    for (int rr = 0; rr < 8; rr++) {
        float rv = rn[ty * 8 + rr];
        float* hp = ho + (size_t)(b * SEQ + i0 + ty * 8 + rr) * DIMV + h * DHEAD + tx * 8;
        float4 o0, o1;
        o0.x = acc[rr][0] * rv; o0.y = acc[rr][1] * rv;
        o0.z = acc[rr][2] * rv; o0.w = acc[rr][3] * rv;
        o1.x = acc[rr][4] * rv; o1.y = acc[rr][5] * rv;
        o1.z = acc[rr][6] * rv; o1.w = acc[rr][7] * rv;
        *(float4*)(hp) = o0;
        *(float4*)(hp + 4) = o1;
    }
}

// ---------------- launcher ---------------------------------------------------
extern "C" void kernel_launch(void* const* d_in, const int* in_sizes, int n_in,
                              void* d_out, int out_size)
{
    const float* x    = (const float*)d_in[0];
    const float* Wqkv = (const float*)d_in[1];
    const float* Wout = (const float*)d_in[2];
    const float* bout = (const float*)d_in[3];
    float* out = (float*)d_out;

    float *qkvp, *Ep, *rp, *rsp, *c1p, *c2p, *c3p, *hop;
    cudaGetSymbolAddress((void**)&qkvp, g_qkv);
    cudaGetSymbolAddress((void**)&Ep,   g_E);
    cudaGetSymbolAddress((void**)&rp,   g_r);
    cudaGetSymbolAddress((void**)&rsp,  g_rowsum);
    cudaGetSymbolAddress((void**)&c1p,  g_cs1);
    cudaGetSymbolAddress((void**)&c2p,  g_cs2);
    cudaGetSymbolAddress((void**)&c3p,  g_cs3);
    cudaGetSymbolAddress((void**)&hop,  g_ho);

    const size_t FIN = (size_t)BQ * SEQ * DIMV;
    const size_t ATT = (size_t)NHEADS * SEQ * SEQ;
    float* fin_ptr = 0;
    float* attn_ptr = 0;
    if ((size_t)out_size >= FIN + ATT) { fin_ptr = out; attn_ptr = out + FIN; }
    else if ((size_t)out_size == ATT)  { attn_ptr = out; }
    else                               { fin_ptr = out; }

    const int NV = NHEADS * SEQ;

    init_sums<<<NV / 256, 256>>>(rsp, c1p, c2p, c3p);

    // 1) qkv = x @ W_qkv
    sgemm128<<<dim3(QKVW / 128, (BQ * SEQ) / 128), 256>>>(
        x, Wqkv, qkvp, BQ * SEQ, QKVW, DIMV, (const float*)0);

    // 2) per 16-head chunk (E slice = 64MB, L2-resident across the 6 passes)
    for (int c0 = 0; c0 < NHEADS; c0 += CH) {
        qk_dots_exp<<<dim3(SEQ / 128, SEQ / 128, CH), 256>>>(qkvp, Ep, rsp, c0);
        colpass<<<dim3(SEQ / 64, CH), 256>>>(Ep, rsp, c1p, c0, 1);   // r1=MU/rowsum
        rowpass<<<dim3(SEQ / 8, CH), 256>>>(Ep, c1p, rp, c0);        // r2
        colpass<<<dim3(SEQ / 64, CH), 256>>>(Ep, rp, c2p, c0, 0);
        rowpass<<<dim3(SEQ / 8, CH), 256>>>(Ep, c2p, rp, c0);        // r3
        colpass<<<dim3(SEQ / 64, CH), 256>>>(Ep, rp, c3p, c0, 0);
    }

    // 3) attn = r*E*c*n (fused write) and ho = attn @ V, per head
    av_gemm<<<dim3(SEQ / 128, NHEADS), 128>>>(
        Ep, rp, c3p, qkvp, attn_ptr ? attn_ptr : Ep, hop, attn_ptr ? 1 : 0);

    // 4) final = ho @ W_out + b_out
    if (fin_ptr)
        sgemm128<<<dim3(DIMV / 128, (BQ * SEQ) / 128), 256>>>(
            hop, Wout, fin_ptr, BQ * SEQ, DIMV, DIMV, bout);
}

// round 4
// speedup vs baseline: 1.0249x; 1.0249x over previous
#include <cuda_runtime.h>
#include <math.h>

#define BQ 8
#define SEQ 1024
#define DIMV 512
#define HEADS 8
#define DHEAD 64
#define NHEADS 64        // BQ*HEADS
#define QKVW 1536        // 3*HEADS*DHEAD

#define MU_C (1.0f/1024.0f)
#define NU_C (1.0f/1024.0f)

typedef unsigned long long u64;

__device__ __forceinline__ u64 dup2(float v) {
    u64 r; asm("mov.b64 %0, {%1, %1};" : "=l"(r) : "f"(v)); return r;
}
__device__ __forceinline__ u64 pk2(float lo, float hi) {
    u64 r; asm("mov.b64 %0, {%1, %2};" : "=l"(r) : "f"(lo), "f"(hi)); return r;
}
__device__ __forceinline__ void ffma2(u64& d, u64 a, u64 b) {
    asm("fma.rn.f32x2 %0, %1, %2, %0;" : "+l"(d) : "l"(a), "l"(b));
}
__device__ __forceinline__ float2 up2(u64 v) {
    float2 f; asm("mov.b64 {%0, %1}, %2;" : "=f"(f.x), "=f"(f.y) : "l"(v)); return f;
}

// ---------------- scratch (device globals; no allocations allowed) ----------
__device__ float g_qkv[(size_t)BQ * SEQ * QKVW];
__device__ float g_E[(size_t)NHEADS * SEQ * SEQ];   // E = exp(-C)
__device__ float g_r[NHEADS * SEQ];
__device__ float g_rowsum[NHEADS * SEQ];
__device__ float g_cs1[NHEADS * SEQ];
__device__ float g_cs2[NHEADS * SEQ];
__device__ float g_cs3[NHEADS * SEQ];
__device__ float g_ho[(size_t)BQ * SEQ * DIMV];

// ---------------- 128x128x8 fp32 GEMM with fma.rn.f32x2 ---------------------
__global__ __launch_bounds__(256) void sgemm128(
    const float* __restrict__ A, const float* __restrict__ Bm,
    float* __restrict__ C, int M, int Nn, int K, const float* __restrict__ bias)
{
    __shared__ float As[8][128];
    __shared__ float Bs[8][128];
    const int t = threadIdx.x;
    const int m0 = blockIdx.y * 128, n0 = blockIdx.x * 128;
    const int alr = t >> 1, alc = (t & 1) * 4;
    const int blr = t >> 5, blc = (t & 31) * 4;
    const int tx = t & 15, ty = t >> 4;

    u64 acc2[8][4];
#pragma unroll
    for (int r = 0; r < 8; r++)
#pragma unroll
        for (int c = 0; c < 4; c++) acc2[r][c] = 0ull;

    for (int k0 = 0; k0 < K; k0 += 8) {
        float4 av = *(const float4*)(A + (size_t)(m0 + alr) * K + k0 + alc);
        As[alc + 0][alr] = av.x; As[alc + 1][alr] = av.y;
        As[alc + 2][alr] = av.z; As[alc + 3][alr] = av.w;
        *(float4*)(&Bs[blr][blc]) =
            *(const float4*)(Bm + (size_t)(k0 + blr) * Nn + n0 + blc);
        __syncthreads();
#pragma unroll
        for (int kk = 0; kk < 8; kk++) {
            float4 A0 = *(const float4*)(&As[kk][ty * 4]);
            float4 A1 = *(const float4*)(&As[kk][64 + ty * 4]);
            u64 b0 = *(const u64*)(&Bs[kk][tx * 4]);
            u64 b1 = *(const u64*)(&Bs[kk][tx * 4 + 2]);
            u64 b2 = *(const u64*)(&Bs[kk][64 + tx * 4]);
            u64 b3 = *(const u64*)(&Bs[kk][64 + tx * 4 + 2]);
            u64 a2[8];
            a2[0] = dup2(A0.x); a2[1] = dup2(A0.y);
            a2[2] = dup2(A0.z); a2[3] = dup2(A0.w);
            a2[4] = dup2(A1.x); a2[5] = dup2(A1.y);
            a2[6] = dup2(A1.z); a2[7] = dup2(A1.w);
#pragma unroll
            for (int r = 0; r < 8; r++) {
                ffma2(acc2[r][0], a2[r], b0);
                ffma2(acc2[r][1], a2[r], b1);
                ffma2(acc2[r][2], a2[r], b2);
                ffma2(acc2[r][3], a2[r], b3);
            }
        }
        __syncthreads();
    }
#pragma unroll
    for (int r = 0; r < 8; r++) {
        int gr = m0 + ((r < 4) ? (ty * 4 + r) : (64 + ty * 4 + (r - 4)));
#pragma unroll
        for (int half = 0; half < 2; half++) {
            int gc = n0 + ((half == 0) ? tx * 4 : 64 + tx * 4);
            float2 p0 = up2(acc2[r][half * 2 + 0]);
            float2 p1 = up2(acc2[r][half * 2 + 1]);
            float4 o; o.x = p0.x; o.y = p0.y; o.z = p1.x; o.w = p1.y;
            if (bias) {
                o.x += bias[gc]; o.y += bias[gc + 1];
                o.z += bias[gc + 2]; o.w += bias[gc + 3];
            }
            *(float4*)(C + (size_t)gr * Nn + gc) = o;
        }
    }
}

// -------- per-head dots -> E = exp(-scale*dots), fused first row-sum --------
__global__ __launch_bounds__(256) void qk_dots_exp(
    const float* __restrict__ qkv, float* __restrict__ E,
    float* __restrict__ rowsum)
{
    const int bh = blockIdx.z, b = bh >> 3, h = bh & 7;
    const int i0 = blockIdx.y * 128, j0 = blockIdx.x * 128;
    const float* qbase = qkv + (size_t)b * SEQ * QKVW + h * DHEAD;
    const float* kbase = qkv + (size_t)b * SEQ * QKVW + 512 + h * DHEAD;

    __shared__ float Qs[8][128];
    __shared__ float Ks[8][128];
    const int t = threadIdx.x;
    const int lr = t >> 1, lc = (t & 1) * 4;
    const int tx = t & 15, ty = t >> 4;

    u64 acc2[8][4];
#pragma unroll
    for (int r = 0; r < 8; r++)
#pragma unroll
        for (int c = 0; c < 4; c++) acc2[r][c] = 0ull;

    for (int k0 = 0; k0 < DHEAD; k0 += 8) {
        float4 qv = *(const float4*)(qbase + (size_t)(i0 + lr) * QKVW + k0 + lc);
        Qs[lc + 0][lr] = qv.x; Qs[lc + 1][lr] = qv.y;
        Qs[lc + 2][lr] = qv.z; Qs[lc + 3][lr] = qv.w;
        float4 kv = *(const float4*)(kbase + (size_t)(j0 + lr) * QKVW + k0 + lc);
        Ks[lc + 0][lr] = kv.x; Ks[lc + 1][lr] = kv.y;
        Ks[lc + 2][lr] = kv.z; Ks[lc + 3][lr] = kv.w;
        __syncthreads();
#pragma unroll
        for (int kk = 0; kk < 8; kk++) {
            float4 A0 = *(const float4*)(&Qs[kk][ty * 4]);
            float4 A1 = *(const float4*)(&Qs[kk][64 + ty * 4]);
            u64 b0 = *(const u64*)(&Ks[kk][tx * 4]);
            u64 b1 = *(const u64*)(&Ks[kk][tx * 4 + 2]);
            u64 b2 = *(const u64*)(&Ks[kk][64 + tx * 4]);
            u64 b3 = *(const u64*)(&Ks[kk][64 + tx * 4 + 2]);
            u64 a2[8];
            a2[0] = dup2(A0.x); a2[1] = dup2(A0.y);
            a2[2] = dup2(A0.z); a2[3] = dup2(A0.w);
            a2[4] = dup2(A1.x); a2[5] = dup2(A1.y);
            a2[6] = dup2(A1.z); a2[7] = dup2(A1.w);
#pragma unroll
            for (int r = 0; r < 8; r++) {
                ffma2(acc2[r][0], a2[r], b0);
                ffma2(acc2[r][1], a2[r], b1);
                ffma2(acc2[r][2], a2[r], b2);
                ffma2(acc2[r][3], a2[r], b3);
            }
        }
        __syncthreads();
    }
    float* Ep = E + (size_t)bh * SEQ * SEQ;
    float rsum[8];
#pragma unroll
    for (int r = 0; r < 8; r++) rsum[r] = 0.f;
#pragma unroll
    for (int r = 0; r < 8; r++) {
        int gi = i0 + ((r < 4) ? (ty * 4 + r) : (64 + ty * 4 + (r - 4)));
#pragma unroll
        for (int half = 0; half < 2; half++) {
            int gj = j0 + ((half == 0) ? tx * 4 : 64 + tx * 4);
            float2 p0 = up2(acc2[r][half * 2 + 0]);
            float2 p1 = up2(acc2[r][half * 2 + 1]);
            float4 o;
            o.x = __expf(-0.125f * p0.x);
            o.y = __expf(-0.125f * p0.y);
            o.z = __expf(-0.125f * p1.x);
            o.w = __expf(-0.125f * p1.y);
            rsum[r] += o.x + o.y + o.z + o.w;
            *(float4*)(Ep + (size_t)gi * SEQ + gj) = o;
        }
    }
#pragma unroll
    for (int r = 0; r < 8; r++) {
#pragma unroll
        for (int off = 1; off < 16; off <<= 1)
            rsum[r] += __shfl_xor_sync(0xffffffffu, rsum[r], off);
    }
    if (tx == 0) {
#pragma unroll
        for (int r = 0; r < 8; r++) {
            int gi = i0 + ((r < 4) ? (ty * 4 + r) : (64 + ty * 4 + (r - 4)));
            atomicAdd(&rowsum[bh * SEQ + gi], rsum[r]);
        }
    }
}

// ---- first col pass: colsum_j += sum_i E_ij * (MU/rowsum_i) ----------------
__global__ __launch_bounds__(256) void colpass1(
    const float* __restrict__ E, const float* __restrict__ rowsum,
    float* __restrict__ colsum)
{
    const int bh = blockIdx.y;
    const int i0 = blockIdx.x * 64;
    const int t = threadIdx.x;
    __shared__ float rs[64];
    if (t < 64) rs[t] = MU_C / rowsum[bh * SEQ + i0 + t];
    __syncthreads();

    const float* Ep = E + (size_t)bh * SEQ * SEQ + (size_t)i0 * SEQ;
    const int j = t * 4;
    float ax = 0.f, ay = 0.f, az = 0.f, aw = 0.f;
#pragma unroll 4
    for (int i = 0; i < 64; i++) {
        float4 e = *(const float4*)(Ep + (size_t)i * SEQ + j);
        float rv = rs[i];
        ax = fmaf(e.x, rv, ax); ay = fmaf(e.y, rv, ay);
        az = fmaf(e.z, rv, az); aw = fmaf(e.w, rv, aw);
    }
    atomicAdd(&colsum[bh * SEQ + j + 0], ax);
    atomicAdd(&colsum[bh * SEQ + j + 1], ay);
    atomicAdd(&colsum[bh * SEQ + j + 2], az);
    atomicAdd(&colsum[bh * SEQ + j + 3], aw);
}

// ---- fused row+col pass: r = MU/(E*(NU/cs_in)); cs_out += E^T r -------------
// block = 256 thr, 32 rows staged in dynamic smem (read E from DRAM once)
__global__ __launch_bounds__(256) void rc_fused(
    const float* __restrict__ E, const float* __restrict__ cs_in,
    float* __restrict__ cs_out, float* __restrict__ rout)
{
    extern __shared__ float sh[];
    float* Es = sh;              // 32*1024
    float* cs = sh + 32 * 1024;  // 1024
    float* rl = cs + 1024;       // 32

    const int bh = blockIdx.y, i0 = blockIdx.x * 32;
    const int t = threadIdx.x, lane = t & 31, w = t >> 5;

#pragma unroll
    for (int q = 0; q < 4; q++) {
        int j = t + 256 * q;
        cs[j] = NU_C / cs_in[bh * SEQ + j];
    }
    __syncthreads();

    const float* Ep = E + (size_t)bh * SEQ * SEQ + (size_t)i0 * SEQ;
    // phase A: warp w owns rows 4w..4w+3
#pragma unroll
    for (int rr = 0; rr < 4; rr++) {
        const int row = w * 4 + rr;
        const float* Er = Ep + (size_t)row * SEQ;
        float acc = 0.f;
#pragma unroll
        for (int it = 0; it < 8; it++) {
            int j = it * 128 + lane * 4;
            float4 e = *(const float4*)(Er + j);
            *(float4*)(&Es[row * 1024 + j]) = e;
            acc += e.x * cs[j] + e.y * cs[j + 1] + e.z * cs[j + 2] + e.w * cs[j + 3];
        }
#pragma unroll
        for (int o = 16; o > 0; o >>= 1)
            acc += __shfl_xor_sync(0xffffffffu, acc, o);
        if (lane == 0) {
            float rv = MU_C / acc;
            rl[row] = rv;
            rout[bh * SEQ + i0 + row] = rv;
        }
    }
    __syncthreads();

    // phase B: column partials from smem
    const int j = t * 4;
    float ax = 0.f, ay = 0.f, az = 0.f, aw = 0.f;
#pragma unroll 8
    for (int i = 0; i < 32; i++) {
        float4 e = *(const float4*)(&Es[i * 1024 + j]);
        float rv = rl[i];
        ax = fmaf(e.x, rv, ax); ay = fmaf(e.y, rv, ay);
        az = fmaf(e.z, rv, az); aw = fmaf(e.w, rv, aw);
    }
    atomicAdd(&cs_out[bh * SEQ + j + 0], ax);
    atomicAdd(&cs_out[bh * SEQ + j + 1], ay);
    atomicAdd(&cs_out[bh * SEQ + j + 2], az);
    atomicAdd(&cs_out[bh * SEQ + j + 3], aw);
}

__global__ void init_sums(float* __restrict__ rowsum, float* __restrict__ c1,
                          float* __restrict__ c2, float* __restrict__ c3)
{
    int i = blockIdx.x * 256 + threadIdx.x;
    rowsum[i] = 0.f; c1[i] = 0.f; c2[i] = 0.f; c3[i] = 0.f;
}

// -------- per-head GEMM: ho = rn_i * (E @ (c_j V)), fused attn write --------
__global__ __launch_bounds__(128) void av_gemm(
    const float* __restrict__ E, const float* __restrict__ r,
    const float* __restrict__ colsum3, const float* __restrict__ qkv,
    float* __restrict__ attn, float* __restrict__ ho, int write_attn)
{
    const int bh = blockIdx.y, b = bh >> 3, h = bh & 7;
    const int i0 = blockIdx.x * 128;
    const int t = threadIdx.x;
    const int tx = t & 7, ty = t >> 3;

    __shared__ float Es[128][33];
    __shared__ float Ws[32][64];
    __shared__ float cr[SEQ];
    __shared__ float rn[128];

    if (t < 128) rn[t] = r[bh * SEQ + i0 + t] * 1024.0f;
#pragma unroll
    for (int q = 0; q < 8; q++) {
        int j = t + 128 * q;
        cr[j] = NU_C / colsum3[bh * SEQ + j];
    }
    __syncthreads();

    const float* Ep = E + (size_t)bh * SEQ * SEQ;
    const float* vb = qkv + (size_t)b * SEQ * QKVW + 1024 + h * DHEAD;
    float* ap = attn + (size_t)bh * SEQ * SEQ;

    u64 acc2[8][4];
#pragma unroll
    for (int rr = 0; rr < 8; rr++)
#pragma unroll
        for (int cc = 0; cc < 4; cc++) acc2[rr][cc] = 0ull;

    for (int jt = 0; jt < 32; jt++) {
        const int j0 = jt * 32;
#pragma unroll
        for (int q = 0; q < 8; q++) {
            int f = t + 128 * q;
            int i = f >> 3, jq = (f & 7) * 4;
            float4 e = *(const float4*)(Ep + (size_t)(i0 + i) * SEQ + j0 + jq);
            Es[i][jq + 0] = e.x; Es[i][jq + 1] = e.y;
            Es[i][jq + 2] = e.z; Es[i][jq + 3] = e.w;
            if (write_attn) {
                float rv = rn[i];
                float4 o;
                o.x = rv * e.x * cr[j0 + jq + 0];
                o.y = rv * e.y * cr[j0 + jq + 1];
                o.z = rv * e.z * cr[j0 + jq + 2];
                o.w = rv * e.w * cr[j0 + jq + 3];
                *(float4*)(ap + (size_t)(i0 + i) * SEQ + j0 + jq) = o;
            }
        }
#pragma unroll
        for (int q = 0; q < 4; q++) {
            int f = t + 128 * q;
            int k = f >> 4, dq = (f & 15) * 4;
            float4 v = *(const float4*)(vb + (size_t)(j0 + k) * QKVW + dq);
            float cw = cr[j0 + k];
            v.x *= cw; v.y *= cw; v.z *= cw; v.w *= cw;
            *(float4*)(&Ws[k][dq]) = v;
        }
        __syncthreads();
#pragma unroll
        for (int kk = 0; kk < 32; kk++) {
            u64 b0 = *(const u64*)(&Ws[kk][tx * 8]);
            u64 b1 = *(const u64*)(&Ws[kk][tx * 8 + 2]);
            u64 b2 = *(const u64*)(&Ws[kk][tx * 8 + 4]);
            u64 b3 = *(const u64*)(&Ws[kk][tx * 8 + 6]);
            u64 a2[8];
#pragma unroll
            for (int rr = 0; rr < 8; rr++) a2[rr] = dup2(Es[ty * 8 + rr][kk]);
#pragma unroll
            for (int rr = 0; rr < 8; rr++) {
                ffma2(acc2[rr][0], a2[rr], b0);
                ffma2(acc2[rr][1], a2[rr], b1);
                ffma2(acc2[rr][2], a2[rr], b2);
                ffma2(acc2[rr][3], a2[rr], b3);
            }
        }
        __syncthreads();
    }
#pragma unroll
    for (int rr = 0; rr < 8; rr++) {
        float rv = rn[ty * 8 + rr];
        float* hp = ho + (size_t)(b * SEQ + i0 + ty * 8 + rr) * DIMV + h * DHEAD + tx * 8;
        float2 p0 = up2(acc2[rr][0]);
        float2 p1 = up2(acc2[rr][1]);
        float2 p2 = up2(acc2[rr][2]);
        float2 p3 = up2(acc2[rr][3]);
        float4 o0, o1;
        o0.x = p0.x * rv; o0.y = p0.y * rv; o0.z = p1.x * rv; o0.w = p1.y * rv;
        o1.x = p2.x * rv; o1.y = p2.y * rv; o1.z = p3.x * rv; o1.w = p3.y * rv;
        *(float4*)(hp) = o0;
        *(float4*)(hp + 4) = o1;
    }
}

// ---------------- launcher ---------------------------------------------------
extern "C" void kernel_launch(void* const* d_in, const int* in_sizes, int n_in,
                              void* d_out, int out_size)
{
    const float* x    = (const float*)d_in[0];
    const float* Wqkv = (const float*)d_in[1];
    const float* Wout = (const float*)d_in[2];
    const float* bout = (const float*)d_in[3];
    float* out = (float*)d_out;

    float *qkvp, *Ep, *rp, *rsp, *c1p, *c2p, *c3p, *hop;
    cudaGetSymbolAddress((void**)&qkvp, g_qkv);
    cudaGetSymbolAddress((void**)&Ep,   g_E);
    cudaGetSymbolAddress((void**)&rp,   g_r);
    cudaGetSymbolAddress((void**)&rsp,  g_rowsum);
    cudaGetSymbolAddress((void**)&c1p,  g_cs1);
    cudaGetSymbolAddress((void**)&c2p,  g_cs2);
    cudaGetSymbolAddress((void**)&c3p,  g_cs3);
    cudaGetSymbolAddress((void**)&hop,  g_ho);

    const size_t FIN = (size_t)BQ * SEQ * DIMV;
    const size_t ATT = (size_t)NHEADS * SEQ * SEQ;
    float* fin_ptr = 0;
    float* attn_ptr = 0;
    if ((size_t)out_size >= FIN + ATT) { fin_ptr = out; attn_ptr = out + FIN; }
    else if ((size_t)out_size == ATT)  { attn_ptr = out; }
    else                               { fin_ptr = out; }

    const int NV = NHEADS * SEQ;
    const int RC_SMEM = (32 * 1024 + 1024 + 32) * 4;   // ~135.3 KB
    cudaFuncSetAttribute(rc_fused, cudaFuncAttributeMaxDynamicSharedMemorySize,
                         RC_SMEM);

    init_sums<<<NV / 256, 256>>>(rsp, c1p, c2p, c3p);

    // 1) qkv = x @ W_qkv
    sgemm128<<<dim3(QKVW / 128, (BQ * SEQ) / 128), 256>>>(
        x, Wqkv, qkvp, BQ * SEQ, QKVW, DIMV, (const float*)0);

    // 2) E = exp(-scale*q k^T), fused rowsum (c0 = 1)
    qk_dots_exp<<<dim3(SEQ / 128, SEQ / 128, NHEADS), 256>>>(qkvp, Ep, rsp);

    // 3) Sinkhorn: col1, then two fused (row+col) passes
    colpass1<<<dim3(SEQ / 64, NHEADS), 256>>>(Ep, rsp, c1p);
    rc_fused<<<dim3(SEQ / 32, NHEADS), 256, RC_SMEM>>>(Ep, c1p, c2p, rp); // r2
    rc_fused<<<dim3(SEQ / 32, NHEADS), 256, RC_SMEM>>>(Ep, c2p, c3p, rp); // r3

    // 4) attn = r*E*c*n (fused write) and ho = attn @ V, per head
    av_gemm<<<dim3(SEQ / 128, NHEADS), 128>>>(
        Ep, rp, c3p, qkvp, attn_ptr ? attn_ptr : Ep, hop, attn_ptr ? 1 : 0);

    // 5) final = ho @ W_out + b_out
    if (fin_ptr)
        sgemm128<<<dim3(DIMV / 128, (BQ * SEQ) / 128), 256>>>(
            hop, Wout, fin_ptr, BQ * SEQ, DIMV, DIMV, bout);
}

// round 5
// speedup vs baseline: 1.1040x; 1.0772x over previous
#include <cuda_runtime.h>
#include <math.h>

#define BQ 8
#define SEQ 1024
#define DIMV 512
#define HEADS 8
#define DHEAD 64
#define NHEADS 64        // BQ*HEADS
#define QKVW 1536        // 3*HEADS*DHEAD

#define MU_C (1.0f/1024.0f)
#define NU_C (1.0f/1024.0f)

typedef unsigned long long u64;

__device__ __forceinline__ u64 dup2(float v) {
    u64 r; asm("mov.b64 %0, {%1, %1};" : "=l"(r) : "f"(v)); return r;
}
__device__ __forceinline__ void ffma2(u64& d, u64 a, u64 b) {
    asm("fma.rn.f32x2 %0, %1, %2, %0;" : "+l"(d) : "l"(a), "l"(b));
}
__device__ __forceinline__ float2 up2(u64 v) {
    float2 f; asm("mov.b64 {%0, %1}, %2;" : "=f"(f.x), "=f"(f.y) : "l"(v)); return f;
}

// ---------------- scratch (device globals; no allocations allowed) ----------
__device__ float g_qkv[(size_t)BQ * SEQ * QKVW];
__device__ float g_E[(size_t)NHEADS * SEQ * SEQ];   // E = exp(-C)
__device__ float g_r[NHEADS * SEQ];
__device__ float g_rowsum[NHEADS * SEQ];
__device__ float g_cs1[NHEADS * SEQ];
__device__ float g_cs2[NHEADS * SEQ];
__device__ float g_cs3[NHEADS * SEQ];
__device__ float g_ho[(size_t)BQ * SEQ * DIMV];

// ---------------- 128x128x8 fp32 GEMM with fma.rn.f32x2 ---------------------
__global__ __launch_bounds__(256) void sgemm128(
    const float* __restrict__ A, const float* __restrict__ Bm,
    float* __restrict__ C, int M, int Nn, int K, const float* __restrict__ bias)
{
    __shared__ float As[8][128];
    __shared__ float Bs[8][128];
    const int t = threadIdx.x;
    const int m0 = blockIdx.y * 128, n0 = blockIdx.x * 128;
    const int alr = t >> 1, alc = (t & 1) * 4;
    const int blr = t >> 5, blc = (t & 31) * 4;
    const int tx = t & 15, ty = t >> 4;

    u64 acc2[8][4];
#pragma unroll
    for (int r = 0; r < 8; r++)
#pragma unroll
        for (int c = 0; c < 4; c++) acc2[r][c] = 0ull;

    for (int k0 = 0; k0 < K; k0 += 8) {
        float4 av = *(const float4*)(A + (size_t)(m0 + alr) * K + k0 + alc);
        As[alc + 0][alr] = av.x; As[alc + 1][alr] = av.y;
        As[alc + 2][alr] = av.z; As[alc + 3][alr] = av.w;
        *(float4*)(&Bs[blr][blc]) =
            *(const float4*)(Bm + (size_t)(k0 + blr) * Nn + n0 + blc);
        __syncthreads();
#pragma unroll
        for (int kk = 0; kk < 8; kk++) {
            float4 A0 = *(const float4*)(&As[kk][ty * 4]);
            float4 A1 = *(const float4*)(&As[kk][64 + ty * 4]);
            u64 b0 = *(const u64*)(&Bs[kk][tx * 4]);
            u64 b1 = *(const u64*)(&Bs[kk][tx * 4 + 2]);
            u64 b2 = *(const u64*)(&Bs[kk][64 + tx * 4]);
            u64 b3 = *(const u64*)(&Bs[kk][64 + tx * 4 + 2]);
            u64 a2[8];
            a2[0] = dup2(A0.x); a2[1] = dup2(A0.y);
            a2[2] = dup2(A0.z); a2[3] = dup2(A0.w);
            a2[4] = dup2(A1.x); a2[5] = dup2(A1.y);
            a2[6] = dup2(A1.z); a2[7] = dup2(A1.w);
#pragma unroll
            for (int r = 0; r < 8; r++) {
                ffma2(acc2[r][0], a2[r], b0);
                ffma2(acc2[r][1], a2[r], b1);
                ffma2(acc2[r][2], a2[r], b2);
                ffma2(acc2[r][3], a2[r], b3);
            }
        }
        __syncthreads();
    }
#pragma unroll
    for (int r = 0; r < 8; r++) {
        int gr = m0 + ((r < 4) ? (ty * 4 + r) : (64 + ty * 4 + (r - 4)));
#pragma unroll
        for (int half = 0; half < 2; half++) {
            int gc = n0 + ((half == 0) ? tx * 4 : 64 + tx * 4);
            float2 p0 = up2(acc2[r][half * 2 + 0]);
            float2 p1 = up2(acc2[r][half * 2 + 1]);
            float4 o; o.x = p0.x; o.y = p0.y; o.z = p1.x; o.w = p1.y;
            if (bias) {
                o.x += bias[gc]; o.y += bias[gc + 1];
                o.z += bias[gc + 2]; o.w += bias[gc + 3];
            }
            *(float4*)(C + (size_t)gr * Nn + gc) = o;
        }
    }
}

// -------- per-head dots -> E = exp(-scale*dots), fused first row-sum --------
__global__ __launch_bounds__(256) void qk_dots_exp(
    const float* __restrict__ qkv, float* __restrict__ E,
    float* __restrict__ rowsum)
{
    const int bh = blockIdx.z, b = bh >> 3, h = bh & 7;
    const int i0 = blockIdx.y * 128, j0 = blockIdx.x * 128;
    const float* qbase = qkv + (size_t)b * SEQ * QKVW + h * DHEAD;
    const float* kbase = qkv + (size_t)b * SEQ * QKVW + 512 + h * DHEAD;

    __shared__ float Qs[8][128];
    __shared__ float Ks[8][128];
    const int t = threadIdx.x;
    const int lr = t >> 1, lc = (t & 1) * 4;
    const int tx = t & 15, ty = t >> 4;

    u64 acc2[8][4];
#pragma unroll
    for (int r = 0; r < 8; r++)
#pragma unroll
        for (int c = 0; c < 4; c++) acc2[r][c] = 0ull;

    for (int k0 = 0; k0 < DHEAD; k0 += 8) {
        float4 qv = *(const float4*)(qbase + (size_t)(i0 + lr) * QKVW + k0 + lc);
        Qs[lc + 0][lr] = qv.x; Qs[lc + 1][lr] = qv.y;
        Qs[lc + 2][lr] = qv.z; Qs[lc + 3][lr] = qv.w;
        float4 kv = *(const float4*)(kbase + (size_t)(j0 + lr) * QKVW + k0 + lc);
        Ks[lc + 0][lr] = kv.x; Ks[lc + 1][lr] = kv.y;
        Ks[lc + 2][lr] = kv.z; Ks[lc + 3][lr] = kv.w;
        __syncthreads();
#pragma unroll
        for (int kk = 0; kk < 8; kk++) {
            float4 A0 = *(const float4*)(&Qs[kk][ty * 4]);
            float4 A1 = *(const float4*)(&Qs[kk][64 + ty * 4]);
            u64 b0 = *(const u64*)(&Ks[kk][tx * 4]);
            u64 b1 = *(const u64*)(&Ks[kk][tx * 4 + 2]);
            u64 b2 = *(const u64*)(&Ks[kk][64 + tx * 4]);
            u64 b3 = *(const u64*)(&Ks[kk][64 + tx * 4 + 2]);
            u64 a2[8];
            a2[0] = dup2(A0.x); a2[1] = dup2(A0.y);
            a2[2] = dup2(A0.z); a2[3] = dup2(A0.w);
            a2[4] = dup2(A1.x); a2[5] = dup2(A1.y);
            a2[6] = dup2(A1.z); a2[7] = dup2(A1.w);
#pragma unroll
            for (int r = 0; r < 8; r++) {
                ffma2(acc2[r][0], a2[r], b0);
                ffma2(acc2[r][1], a2[r], b1);
                ffma2(acc2[r][2], a2[r], b2);
                ffma2(acc2[r][3], a2[r], b3);
            }
        }
        __syncthreads();
    }
    float* Ep = E + (size_t)bh * SEQ * SEQ;
    float rsum[8];
#pragma unroll
    for (int r = 0; r < 8; r++) rsum[r] = 0.f;
#pragma unroll
    for (int r = 0; r < 8; r++) {
        int gi = i0 + ((r < 4) ? (ty * 4 + r) : (64 + ty * 4 + (r - 4)));
#pragma unroll
        for (int half = 0; half < 2; half++) {
            int gj = j0 + ((half == 0) ? tx * 4 : 64 + tx * 4);
            float2 p0 = up2(acc2[r][half * 2 + 0]);
            float2 p1 = up2(acc2[r][half * 2 + 1]);
            float4 o;
            o.x = __expf(-0.125f * p0.x);
            o.y = __expf(-0.125f * p0.y);
            o.z = __expf(-0.125f * p1.x);
            o.w = __expf(-0.125f * p1.y);
            rsum[r] += o.x + o.y + o.z + o.w;
            *(float4*)(Ep + (size_t)gi * SEQ + gj) = o;
        }
    }
#pragma unroll
    for (int r = 0; r < 8; r++) {
#pragma unroll
        for (int off = 1; off < 16; off <<= 1)
            rsum[r] += __shfl_xor_sync(0xffffffffu, rsum[r], off);
    }
    if (tx == 0) {
#pragma unroll
        for (int r = 0; r < 8; r++) {
            int gi = i0 + ((r < 4) ? (ty * 4 + r) : (64 + ty * 4 + (r - 4)));
            atomicAdd(&rowsum[bh * SEQ + gi], rsum[r]);
        }
    }
}

// ---- col pass: colsum_j += sum_i E_ij * rs_i  (rs from rowsum or r) --------
__global__ __launch_bounds__(256) void colpass(
    const float* __restrict__ E, const float* __restrict__ rvec,
    float* __restrict__ colsum, int recip)
{
    const int bh = blockIdx.y;
    const int i0 = blockIdx.x * 64;
    const int t = threadIdx.x;
    __shared__ float rs[64];
    if (t < 64) {
        float rv = rvec[bh * SEQ + i0 + t];
        rs[t] = recip ? (MU_C / rv) : rv;
    }
    __syncthreads();

    const float* Ep = E + (size_t)bh * SEQ * SEQ + (size_t)i0 * SEQ;
    const int j = t * 4;
    float ax = 0.f, ay = 0.f, az = 0.f, aw = 0.f;
#pragma unroll 4
    for (int i = 0; i < 64; i++) {
        float4 e = *(const float4*)(Ep + (size_t)i * SEQ + j);
        float rv = rs[i];
        ax = fmaf(e.x, rv, ax); ay = fmaf(e.y, rv, ay);
        az = fmaf(e.z, rv, az); aw = fmaf(e.w, rv, aw);
    }
    atomicAdd(&colsum[bh * SEQ + j + 0], ax);
    atomicAdd(&colsum[bh * SEQ + j + 1], ay);
    atomicAdd(&colsum[bh * SEQ + j + 2], az);
    atomicAdd(&colsum[bh * SEQ + j + 3], aw);
}

// ---- row pass: r_i = MU / sum_j E_ij * (NU/colsum_j)  (one warp per row) ---
__global__ __launch_bounds__(256) void rowpass(
    const float* __restrict__ E, const float* __restrict__ colsum,
    float* __restrict__ r)
{
    const int bh = blockIdx.y;
    const int t = threadIdx.x, lane = t & 31, w = t >> 5;
    const int row = blockIdx.x * 8 + w;
    __shared__ float cs[SEQ];
    {
        float4 cv = *(const float4*)(colsum + bh * SEQ + t * 4);
        cs[t * 4 + 0] = NU_C / cv.x;
        cs[t * 4 + 1] = NU_C / cv.y;
        cs[t * 4 + 2] = NU_C / cv.z;
        cs[t * 4 + 3] = NU_C / cv.w;
    }
    __syncthreads();

    const float* Er = E + (size_t)bh * SEQ * SEQ + (size_t)row * SEQ;
    float acc = 0.f;
#pragma unroll
    for (int it = 0; it < 8; it++) {
        int j = it * 128 + lane * 4;
        float4 e = *(const float4*)(Er + j);
        acc += e.x * cs[j] + e.y * cs[j + 1] + e.z * cs[j + 2] + e.w * cs[j + 3];
    }
#pragma unroll
    for (int o = 16; o > 0; o >>= 1)
        acc += __shfl_xor_sync(0xffffffffu, acc, o);
    if (lane == 0) r[bh * SEQ + row] = MU_C / acc;
}

__global__ void init_sums(float* __restrict__ rowsum, float* __restrict__ c1,
                          float* __restrict__ c2, float* __restrict__ c3)
{
    int i = blockIdx.x * 256 + threadIdx.x;
    rowsum[i] = 0.f; c1[i] = 0.f; c2[i] = 0.f; c3[i] = 0.f;
}

// -------- per-head GEMM: ho = rn_i * (E @ (c_j V)), fused attn write --------
__global__ __launch_bounds__(128) void av_gemm(
    const float* __restrict__ E, const float* __restrict__ r,
    const float* __restrict__ colsum3, const float* __restrict__ qkv,
    float* __restrict__ attn, float* __restrict__ ho, int write_attn)
{
    const int bh = blockIdx.y, b = bh >> 3, h = bh & 7;
    const int i0 = blockIdx.x * 128;
    const int t = threadIdx.x;
    const int tx = t & 7, ty = t >> 3;

    __shared__ float Es[128][33];
    __shared__ float Ws[32][64];
    __shared__ float cr[SEQ];
    __shared__ float rn[128];

    if (t < 128) rn[t] = r[bh * SEQ + i0 + t] * 1024.0f;
#pragma unroll
    for (int q = 0; q < 8; q++) {
        int j = t + 128 * q;
        cr[j] = NU_C / colsum3[bh * SEQ + j];
    }
    __syncthreads();

    const float* Ep = E + (size_t)bh * SEQ * SEQ;
    const float* vb = qkv + (size_t)b * SEQ * QKVW + 1024 + h * DHEAD;
    float* ap = attn + (size_t)bh * SEQ * SEQ;

    u64 acc2[8][4];
#pragma unroll
    for (int rr = 0; rr < 8; rr++)
#pragma unroll
        for (int cc = 0; cc < 4; cc++) acc2[rr][cc] = 0ull;

    for (int jt = 0; jt < 32; jt++) {
        const int j0 = jt * 32;
#pragma unroll
        for (int q = 0; q < 8; q++) {
            int f = t + 128 * q;
            int i = f >> 3, jq = (f & 7) * 4;
            float4 e = *(const float4*)(Ep + (size_t)(i0 + i) * SEQ + j0 + jq);
            Es[i][jq + 0] = e.x; Es[i][jq + 1] = e.y;
            Es[i][jq + 2] = e.z; Es[i][jq + 3] = e.w;
            if (write_attn) {
                float rv = rn[i];
                float4 o;
                o.x = rv * e.x * cr[j0 + jq + 0];
                o.y = rv * e.y * cr[j0 + jq + 1];
                o.z = rv * e.z * cr[j0 + jq + 2];
                o.w = rv * e.w * cr[j0 + jq + 3];
                *(float4*)(ap + (size_t)(i0 + i) * SEQ + j0 + jq) = o;
            }
        }
#pragma unroll
        for (int q = 0; q < 4; q++) {
            int f = t + 128 * q;
            int k = f >> 4, dq = (f & 15) * 4;
            float4 v = *(const float4*)(vb + (size_t)(j0 + k) * QKVW + dq);
            float cw = cr[j0 + k];
            v.x *= cw; v.y *= cw; v.z *= cw; v.w *= cw;
            *(float4*)(&Ws[k][dq]) = v;
        }
        __syncthreads();
#pragma unroll
        for (int kk = 0; kk < 32; kk++) {
            u64 b0 = *(const u64*)(&Ws[kk][tx * 8]);
            u64 b1 = *(const u64*)(&Ws[kk][tx * 8 + 2]);
            u64 b2 = *(const u64*)(&Ws[kk][tx * 8 + 4]);
            u64 b3 = *(const u64*)(&Ws[kk][tx * 8 + 6]);
            u64 a2[8];
#pragma unroll
            for (int rr = 0; rr < 8; rr++) a2[rr] = dup2(Es[ty * 8 + rr][kk]);
#pragma unroll
            for (int rr = 0; rr < 8; rr++) {
                ffma2(acc2[rr][0], a2[rr], b0);
                ffma2(acc2[rr][1], a2[rr], b1);
                ffma2(acc2[rr][2], a2[rr], b2);
                ffma2(acc2[rr][3], a2[rr], b3);
            }
        }
        __syncthreads();
    }
#pragma unroll
    for (int rr = 0; rr < 8; rr++) {
        float rv = rn[ty * 8 + rr];
        float* hp = ho + (size_t)(b * SEQ + i0 + ty * 8 + rr) * DIMV + h * DHEAD + tx * 8;
        float2 p0 = up2(acc2[rr][0]);
        float2 p1 = up2(acc2[rr][1]);
        float2 p2 = up2(acc2[rr][2]);
        float2 p3 = up2(acc2[rr][3]);
        float4 o0, o1;
        o0.x = p0.x * rv; o0.y = p0.y * rv; o0.z = p1.x * rv; o0.w = p1.y * rv;
        o1.x = p2.x * rv; o1.y = p2.y * rv; o1.z = p3.x * rv; o1.w = p3.y * rv;
        *(float4*)(hp) = o0;
        *(float4*)(hp + 4) = o1;
    }
}

// ---------------- launcher ---------------------------------------------------
extern "C" void kernel_launch(void* const* d_in, const int* in_sizes, int n_in,
                              void* d_out, int out_size)
{
    const float* x    = (const float*)d_in[0];
    const float* Wqkv = (const float*)d_in[1];
    const float* Wout = (const float*)d_in[2];
    const float* bout = (const float*)d_in[3];
    float* out = (float*)d_out;

    float *qkvp, *Ep, *rp, *rsp, *c1p, *c2p, *c3p, *hop;
    cudaGetSymbolAddress((void**)&qkvp, g_qkv);
    cudaGetSymbolAddress((void**)&Ep,   g_E);
    cudaGetSymbolAddress((void**)&rp,   g_r);
    cudaGetSymbolAddress((void**)&rsp,  g_rowsum);
    cudaGetSymbolAddress((void**)&c1p,  g_cs1);
    cudaGetSymbolAddress((void**)&c2p,  g_cs2);
    cudaGetSymbolAddress((void**)&c3p,  g_cs3);
    cudaGetSymbolAddress((void**)&hop,  g_ho);

    const size_t FIN = (size_t)BQ * SEQ * DIMV;
    const size_t ATT = (size_t)NHEADS * SEQ * SEQ;
    float* fin_ptr = 0;
    float* attn_ptr = 0;
    if ((size_t)out_size >= FIN + ATT) { fin_ptr = out; attn_ptr = out + FIN; }
    else if ((size_t)out_size == ATT)  { attn_ptr = out; }
    else                               { fin_ptr = out; }

    const int NV = NHEADS * SEQ;

    init_sums<<<NV / 256, 256>>>(rsp, c1p, c2p, c3p);

    // 1) qkv = x @ W_qkv
    sgemm128<<<dim3(QKVW / 128, (BQ * SEQ) / 128), 256>>>(
        x, Wqkv, qkvp, BQ * SEQ, QKVW, DIMV, (const float*)0);

    // 2) E = exp(-scale*q k^T), fused rowsum (c0 = 1)
    qk_dots_exp<<<dim3(SEQ / 128, SEQ / 128, NHEADS), 256>>>(qkvp, Ep, rsp);

    // 3) Sinkhorn: col1, row2, col2, row3, col3 (all bandwidth-shaped)
    colpass<<<dim3(SEQ / 64, NHEADS), 256>>>(Ep, rsp, c1p, 1);
    rowpass<<<dim3(SEQ / 8, NHEADS), 256>>>(Ep, c1p, rp);
    colpass<<<dim3(SEQ / 64, NHEADS), 256>>>(Ep, rp, c2p, 0);
    rowpass<<<dim3(SEQ / 8, NHEADS), 256>>>(Ep, c2p, rp);
    colpass<<<dim3(SEQ / 64, NHEADS), 256>>>(Ep, rp, c3p, 0);

    // 4) attn = r*E*c*n (fused write) and ho = attn @ V, per head
    av_gemm<<<dim3(SEQ / 128, NHEADS), 128>>>(
        Ep, rp, c3p, qkvp, attn_ptr ? attn_ptr : Ep, hop, attn_ptr ? 1 : 0);

    // 5) final = ho @ W_out + b_out
    if (fin_ptr)
        sgemm128<<<dim3(DIMV / 128, (BQ * SEQ) / 128), 256>>>(
            hop, Wout, fin_ptr, BQ * SEQ, DIMV, DIMV, bout);
}